// round 1
// baseline (speedup 1.0000x reference)
#include <cuda_runtime.h>

// SSIM loss: pred/target fp32 (8,8,3,256,256) -> scalar 1 - mean(ssim_map)
// 192 planes of 256x256. Depthwise 11x11 Gaussian (sigma=1.5), separable.

#define HW       256
#define PLANE    (HW * HW)
#define NPLANES  192
#define TILES_X  8
#define TILES_Y  8
#define NBLOCKS  (TILES_X * TILES_Y * NPLANES)   // 12288
#define NTHREADS 256
#define NPIX     12582912.0f                      // 192*256*256

__device__ float g_partials[NBLOCKS];

__device__ __forceinline__ float clip01(float v) { return fminf(fmaxf(v, 0.0f), 1.0f); }

// Normalized Gaussian weights for ws=11, sigma=1.5 (compile-time constants so
// ptxas emits immediate-form FFMA: rt_SMSP=1 instead of 2).
#define GW0 0.00102838f
#define GW1 0.00759872f
#define GW2 0.03600084f
#define GW3 0.10936034f
#define GW4 0.21300566f
#define GW5 0.26601220f

__global__ __launch_bounds__(NTHREADS) void ssim_main(
    const float* __restrict__ pred, const float* __restrict__ targ)
{
    // Horizontal-conv intermediates: 42 rows (32 out + 2*5 halo) x 32 cols, 5 quantities
    __shared__ float s_int[5][42 * 32];   // 26880 B
    // Vertical results: 32x32, 5 quantities
    __shared__ float s_fin[5][32 * 32];   // 20480 B
    __shared__ float s_red[8];

    const int tid = threadIdx.x;
    const int ox = blockIdx.x * 32;
    const int oy = blockIdx.y * 32;
    const int plane = blockIdx.z;
    const float* __restrict__ px = pred + (size_t)plane * PLANE;
    const float* __restrict__ py = targ + (size_t)plane * PLANE;

    const float W[11] = {GW0, GW1, GW2, GW3, GW4, GW5, GW4, GW3, GW2, GW1, GW0};

    // ---- Phase A: fused global load + products + horizontal conv ----
    // Tasks: 42 rows x 8 col-groups (4 outputs each) = 336
    for (int task = tid; task < 42 * 8; task += NTHREADS) {
        const int r  = task >> 3;
        const int c0 = (task & 7) * 4;
        const int gy = oy + r - 5;

        if ((unsigned)gy >= (unsigned)HW) {
            const float4 z = make_float4(0.f, 0.f, 0.f, 0.f);
            #pragma unroll
            for (int q = 0; q < 5; q++)
                *reinterpret_cast<float4*>(&s_int[q][r * 32 + c0]) = z;
        } else {
            const float* __restrict__ rx = px + gy * HW;
            const float* __restrict__ ry = py + gy * HW;
            const int gx0 = ox + c0 - 5;

            float xv[14], yv[14];
            #pragma unroll
            for (int i = 0; i < 14; i++) {
                const int gx = gx0 + i;
                const bool ok = (unsigned)gx < (unsigned)HW;
                xv[i] = ok ? clip01(__ldg(rx + gx)) : 0.0f;
                yv[i] = ok ? clip01(__ldg(ry + gx)) : 0.0f;
            }

            // q0: x
            {
                float a0 = 0.f, a1 = 0.f, a2 = 0.f, a3 = 0.f;
                #pragma unroll
                for (int k = 0; k < 11; k++) {
                    a0 = fmaf(W[k], xv[k],     a0);
                    a1 = fmaf(W[k], xv[k + 1], a1);
                    a2 = fmaf(W[k], xv[k + 2], a2);
                    a3 = fmaf(W[k], xv[k + 3], a3);
                }
                *reinterpret_cast<float4*>(&s_int[0][r * 32 + c0]) = make_float4(a0, a1, a2, a3);
            }
            // q1: y
            {
                float a0 = 0.f, a1 = 0.f, a2 = 0.f, a3 = 0.f;
                #pragma unroll
                for (int k = 0; k < 11; k++) {
                    a0 = fmaf(W[k], yv[k],     a0);
                    a1 = fmaf(W[k], yv[k + 1], a1);
                    a2 = fmaf(W[k], yv[k + 2], a2);
                    a3 = fmaf(W[k], yv[k + 3], a3);
                }
                *reinterpret_cast<float4*>(&s_int[1][r * 32 + c0]) = make_float4(a0, a1, a2, a3);
            }
            // q2: x*x, q3: y*y, q4: x*y
            float v[14];
            #pragma unroll
            for (int i = 0; i < 14; i++) v[i] = xv[i] * xv[i];
            {
                float a0 = 0.f, a1 = 0.f, a2 = 0.f, a3 = 0.f;
                #pragma unroll
                for (int k = 0; k < 11; k++) {
                    a0 = fmaf(W[k], v[k],     a0);
                    a1 = fmaf(W[k], v[k + 1], a1);
                    a2 = fmaf(W[k], v[k + 2], a2);
                    a3 = fmaf(W[k], v[k + 3], a3);
                }
                *reinterpret_cast<float4*>(&s_int[2][r * 32 + c0]) = make_float4(a0, a1, a2, a3);
            }
            #pragma unroll
            for (int i = 0; i < 14; i++) v[i] = yv[i] * yv[i];
            {
                float a0 = 0.f, a1 = 0.f, a2 = 0.f, a3 = 0.f;
                #pragma unroll
                for (int k = 0; k < 11; k++) {
                    a0 = fmaf(W[k], v[k],     a0);
                    a1 = fmaf(W[k], v[k + 1], a1);
                    a2 = fmaf(W[k], v[k + 2], a2);
                    a3 = fmaf(W[k], v[k + 3], a3);
                }
                *reinterpret_cast<float4*>(&s_int[3][r * 32 + c0]) = make_float4(a0, a1, a2, a3);
            }
            #pragma unroll
            for (int i = 0; i < 14; i++) v[i] = xv[i] * yv[i];
            {
                float a0 = 0.f, a1 = 0.f, a2 = 0.f, a3 = 0.f;
                #pragma unroll
                for (int k = 0; k < 11; k++) {
                    a0 = fmaf(W[k], v[k],     a0);
                    a1 = fmaf(W[k], v[k + 1], a1);
                    a2 = fmaf(W[k], v[k + 2], a2);
                    a3 = fmaf(W[k], v[k + 3], a3);
                }
                *reinterpret_cast<float4*>(&s_int[4][r * 32 + c0]) = make_float4(a0, a1, a2, a3);
            }
        }
    }
    __syncthreads();

    // ---- Phase B: vertical conv with 8-output register blocking ----
    // Tasks: 5 quantities x 4 row-groups (8 rows) x 32 cols = 640
    for (int task = tid; task < 640; task += NTHREADS) {
        const int q   = task >> 7;
        const int rem = task & 127;
        const int rg  = rem >> 5;
        const int c   = rem & 31;
        const int r0  = rg * 8;

        float v[18];
        #pragma unroll
        for (int k = 0; k < 18; k++) v[k] = s_int[q][(r0 + k) * 32 + c];

        #pragma unroll
        for (int j = 0; j < 8; j++) {
            float a = 0.f;
            #pragma unroll
            for (int k = 0; k < 11; k++) a = fmaf(W[k], v[j + k], a);
            s_fin[q][(r0 + j) * 32 + c] = a;
        }
    }
    __syncthreads();

    // ---- Phase C: SSIM map + block reduction ----
    float lsum = 0.0f;
    #pragma unroll
    for (int i = 0; i < 4; i++) {
        const int idx = tid + i * NTHREADS;
        const float mx = s_fin[0][idx];
        const float my = s_fin[1][idx];
        const float xx = s_fin[2][idx];
        const float yy = s_fin[3][idx];
        const float xy = s_fin[4][idx];

        const float mx2 = mx * mx;
        const float my2 = my * my;
        const float mxy = mx * my;
        const float sx  = fmaxf(xx - mx2, 0.0f);
        const float sy  = fmaxf(yy - my2, 0.0f);
        const float sxy = xy - mxy;

        const float num = (2.0f * mxy + 1e-4f) * (2.0f * sxy + 9e-4f);
        const float den = (mx2 + my2 + 1e-4f) * (sx + sy + 9e-4f);
        float s = num / (den + 1e-8f);
        if (!isfinite(s)) s = 0.0f;
        lsum += s;
    }

    #pragma unroll
    for (int o = 16; o > 0; o >>= 1)
        lsum += __shfl_down_sync(0xffffffffu, lsum, o);
    if ((tid & 31) == 0) s_red[tid >> 5] = lsum;
    __syncthreads();
    if (tid == 0) {
        float v = 0.0f;
        #pragma unroll
        for (int w = 0; w < 8; w++) v += s_red[w];
        const int bid = (blockIdx.z * TILES_Y + blockIdx.y) * TILES_X + blockIdx.x;
        g_partials[bid] = v;
    }
}

__global__ __launch_bounds__(256) void ssim_reduce(float* __restrict__ out)
{
    __shared__ double sr[256];
    double s = 0.0;
    for (int i = threadIdx.x; i < NBLOCKS; i += 256)
        s += (double)g_partials[i];
    sr[threadIdx.x] = s;
    __syncthreads();
    for (int off = 128; off > 0; off >>= 1) {
        if (threadIdx.x < off) sr[threadIdx.x] += sr[threadIdx.x + off];
        __syncthreads();
    }
    if (threadIdx.x == 0)
        out[0] = 1.0f - (float)(sr[0] / (double)NPIX);
}

extern "C" void kernel_launch(void* const* d_in, const int* in_sizes, int n_in,
                              void* d_out, int out_size)
{
    const float* pred = (const float*)d_in[0];
    const float* targ = (const float*)d_in[1];
    dim3 grid(TILES_X, TILES_Y, NPLANES);
    ssim_main<<<grid, NTHREADS>>>(pred, targ);
    ssim_reduce<<<1, 256>>>((float*)d_out);
}